// round 13
// baseline (speedup 1.0000x reference)
#include <cuda_runtime.h>
#include <cuda_fp16.h>
#include <math.h>
#include <stdint.h>

#define CC 256
#define HWSZ 4096
#define BATCH 4
#define NHEAD 4
#define NBH 16

// -------- scratch (device globals; no allocations allowed) --------
__device__ __half g_ht [(size_t)BATCH * HWSZ * CC];      // normalized input, [b][tok][c] half
__device__ __half g_oh [(size_t)BATCH * HWSZ * CC];      // attention out, [b][tok][c] half
__device__ __half g_qh [(size_t)NBH * HWSZ * 64];        // q: [bh][tok][c] half, *0.125*log2e
__device__ __half g_kh [(size_t)NBH * HWSZ * 64];        // k: [bh][tok][c] half
__device__ __half g_vh [(size_t)NBH * 64 * HWSZ];        // v: [bh][c][tok] half
__device__ __half g_wqkv[768 * 256];                     // fp16 weights
__device__ __half g_wproj[256 * 256];
__device__ float2 g_part[1024];                          // per-slice (sum, sumsq)
__device__ float2 g_stats[32];                           // per (b,group) (mean, rstd)

// ============================================================
// helpers (sm_80-baseline PTX only)
// ============================================================
__device__ __forceinline__ uint32_t smem_u32(const void* p) {
    uint32_t a;
    asm("{ .reg .u64 t; cvta.to.shared.u64 t, %1; cvt.u32.u64 %0, t; }" : "=r"(a) : "l"(p));
    return a;
}
__device__ __forceinline__ float ex2f(float x) {
    float r;
    asm("ex2.approx.ftz.f32 %0, %1;" : "=f"(r) : "f"(x));
    return r;
}
__device__ __forceinline__ uint32_t pack_h2(float lo, float hi) {
    uint32_t d;
    asm("cvt.rn.f16x2.f32 %0, %1, %2;" : "=r"(d) : "f"(hi), "f"(lo));
    return d;
}
__device__ __forceinline__ void cp16(uint32_t dst, const void* src) {
    asm volatile("cp.async.cg.shared.global [%0], [%1], 16;" :: "r"(dst), "l"(src) : "memory");
}
#define CP_COMMIT()  asm volatile("cp.async.commit_group;" ::: "memory")
#define CP_WAIT0()   asm volatile("cp.async.wait_group 0;" ::: "memory")

__device__ __forceinline__ void ldsm4(uint32_t r[4], uint32_t addr) {
    asm volatile("ldmatrix.sync.aligned.m8n8.x4.shared.b16 {%0,%1,%2,%3}, [%4];"
        : "=r"(r[0]), "=r"(r[1]), "=r"(r[2]), "=r"(r[3]) : "r"(addr));
}

// fp16 m16n8k16, fp32 accum
__device__ __forceinline__ void mma16(float c[4], const uint32_t a_[4], uint32_t b0, uint32_t b1) {
    asm volatile("mma.sync.aligned.m16n8k16.row.col.f32.f16.f16.f32 "
        "{%0,%1,%2,%3}, {%4,%5,%6,%7}, {%8,%9}, {%0,%1,%2,%3};"
        : "+f"(c[0]), "+f"(c[1]), "+f"(c[2]), "+f"(c[3])
        : "r"(a_[0]), "r"(a_[1]), "r"(a_[2]), "r"(a_[3]),
          "r"(b0), "r"(b1));
}

// ============================================================
// Weight conversion fp32 -> fp16 (vectorized; once per launch)
// ============================================================
__global__ void convert_w_kernel(const float* __restrict__ qkv_w,
                                 const float* __restrict__ proj_w) {
    int i = (blockIdx.x * 256 + threadIdx.x) * 4;
    float4 v;
    __half2 h0, h1;
    if (i < 768 * 256) {
        v = *(const float4*)(qkv_w + i);
        h0 = __floats2half2_rn(v.x, v.y);
        h1 = __floats2half2_rn(v.z, v.w);
        *(__half2*)(g_wqkv + i)     = h0;
        *(__half2*)(g_wqkv + i + 2) = h1;
    } else {
        int k = i - 768 * 256;
        v = *(const float4*)(proj_w + k);
        h0 = __floats2half2_rn(v.x, v.y);
        h1 = __floats2half2_rn(v.z, v.w);
        *(__half2*)(g_wproj + k)     = h0;
        *(__half2*)(g_wproj + k + 2) = h1;
    }
}

// ============================================================
// GroupNorm, 3 phases (unchanged)
// ============================================================
__global__ void gn_partial_kernel(const float* __restrict__ x) {
    const float* xp = x + (size_t)blockIdx.x * 4096;
    int tid = threadIdx.x;
    float s = 0.f, ss = 0.f;
    #pragma unroll 8
    for (int i = tid * 4; i < 4096; i += 512) {
        float4 v = *(const float4*)(xp + i);
        s  += v.x + v.y + v.z + v.w;
        ss += v.x * v.x + v.y * v.y + v.z * v.z + v.w * v.w;
    }
    __shared__ float rs[128], rss[128];
    rs[tid] = s; rss[tid] = ss;
    __syncthreads();
    for (int o = 64; o > 0; o >>= 1) {
        if (tid < o) { rs[tid] += rs[tid + o]; rss[tid] += rss[tid + o]; }
        __syncthreads();
    }
    if (tid == 0) g_part[blockIdx.x] = make_float2(rs[0], rss[0]);
}

__global__ void gn_final_kernel() {
    int t = threadIdx.x;
    float s = 0.f, ss = 0.f;
    #pragma unroll
    for (int i = 0; i < 32; i++) { float2 p = g_part[t * 32 + i]; s += p.x; ss += p.y; }
    float mean = s / 131072.f;
    float var  = ss / 131072.f - mean * mean;
    g_stats[t] = make_float2(mean, rsqrtf(var + 1e-5f));
}

__global__ void gn_norm_kernel(const float* __restrict__ x,
                               const float* __restrict__ w,
                               const float* __restrict__ b) {
    __shared__ float tile[32][129];
    const int t0 = blockIdx.x * 128;
    const int bg = blockIdx.y;
    const int bb = bg >> 3, gg = bg & 7;
    const int tid = threadIdx.x;

    const float* xp = x + ((size_t)bb * 256 + gg * 32) * HWSZ + t0;
    #pragma unroll 4
    for (int i = tid; i < 1024; i += 256) {
        int row = i >> 5, c4 = i & 31;
        float4 v = *(const float4*)(xp + (size_t)row * HWSZ + c4 * 4);
        tile[row][c4 * 4 + 0] = v.x;
        tile[row][c4 * 4 + 1] = v.y;
        tile[row][c4 * 4 + 2] = v.z;
        tile[row][c4 * 4 + 3] = v.w;
    }
    float2 st = g_stats[bg];
    __syncthreads();

    const int tok = tid >> 1, seg = tid & 1;
    __half hv[16];
    #pragma unroll
    for (int i = 0; i < 16; i++) {
        int cc = seg * 16 + i;
        int c = gg * 32 + cc;
        float sc = st.y * w[c];
        float of = b[c] - st.x * sc;
        hv[i] = __float2half_rn(tile[cc][tok] * sc + of);
    }
    __half* dst = g_ht + ((size_t)bb * HWSZ + t0 + tok) * 256 + gg * 32 + seg * 16;
    *(uint4*)dst       = *(uint4*)hv;
    *(uint4*)(dst + 8) = *(uint4*)(hv + 8);
}

// ============================================================
// QKV GEMM: 256x128 tiles. 3 m-tiles (q / k / v), 8 warps (4x2),
// warp = 64 rows x 64 toks. BK=32 double-buffered. Smem-staged epilogue.
// ============================================================
#define QLDW 20
#define QA_TW (256 * QLDW)               // words per A stage
#define QB_TW (128 * QLDW)               // words per B stage
#define QKV_SMEM_BYTES 71680             // max(mainloop 61440, epilogue ~69632)
#define QSCALE 0.18033688011112042f

__global__ void __launch_bounds__(256) gemm_qkv256_kernel(
        const __half* __restrict__ A,
        const __half* __restrict__ Bt,
        const float* __restrict__ bias) {
    extern __shared__ uint32_t sw[];
    uint32_t* a_s = sw;                       // 2 stages [256][20w]
    uint32_t* b_s = sw + 2 * QA_TW;           // 2 stages [128][20w]
    const uint32_t a_u = smem_u32(a_s);
    const uint32_t b_u = smem_u32(b_s);

    const int tid = threadIdx.x, lane = tid & 31, wid = tid >> 5;
    const int g4 = lane >> 2, t4 = lane & 3;
    const int wm = wid >> 1, wn = wid & 1;
    const int bb = blockIdx.z;
    const int m0 = blockIdx.y * 256;          // 0=q, 256=k, 512=v
    const int n0 = blockIdx.x * 128;
    const __half* Bp = Bt + (size_t)bb * HWSZ * 256 + (size_t)n0 * 256;

    float acc[4][8][4];
    #pragma unroll
    for (int mt = 0; mt < 4; mt++)
        #pragma unroll
        for (int nt = 0; nt < 8; nt++)
            #pragma unroll
            for (int i = 0; i < 4; i++) acc[mt][nt][i] = 0.f;

    // prologue: stage 0
    #pragma unroll 4
    for (int e = tid; e < 1024; e += 256) {
        int r = e >> 2, c8 = e & 3;
        cp16(a_u + (r * QLDW + c8 * 4) * 4, A + (size_t)(m0 + r) * 256 + c8 * 8);
    }
    #pragma unroll 2
    for (int e = tid; e < 512; e += 256) {
        int r = e >> 2, c8 = e & 3;
        cp16(b_u + (r * QLDW + c8 * 4) * 4, Bp + (size_t)r * 256 + c8 * 8);
    }
    CP_COMMIT();

    for (int j = 0; j < 8; j++) {
        const int buf = j & 1;
        const uint32_t* at = a_s + buf * QA_TW;
        const uint32_t* bt = b_s + buf * QB_TW;

        CP_WAIT0();
        __syncthreads();

        if (j < 7) {
            const uint32_t ad = a_u + ((buf ^ 1) * QA_TW) * 4;
            const uint32_t bd = b_u + ((buf ^ 1) * QB_TW) * 4;
            const int k0 = (j + 1) * 32;
            #pragma unroll 4
            for (int e = tid; e < 1024; e += 256) {
                int r = e >> 2, c8 = e & 3;
                cp16(ad + (r * QLDW + c8 * 4) * 4, A + (size_t)(m0 + r) * 256 + k0 + c8 * 8);
            }
            #pragma unroll 2
            for (int e = tid; e < 512; e += 256) {
                int r = e >> 2, c8 = e & 3;
                cp16(bd + (r * QLDW + c8 * 4) * 4, Bp + (size_t)r * 256 + k0 + c8 * 8);
            }
            CP_COMMIT();
        }

        #pragma unroll
        for (int kt = 0; kt < 2; kt++) {
            uint32_t af[4][4];
            #pragma unroll
            for (int mt = 0; mt < 4; mt++) {
                const uint32_t* ap = at + (wm * 64 + mt * 16 + g4) * QLDW + kt * 8 + t4;
                af[mt][0] = ap[0];
                af[mt][1] = ap[8 * QLDW];
                af[mt][2] = ap[4];
                af[mt][3] = ap[8 * QLDW + 4];
            }
            const uint32_t* bp = bt + (wn * 64 + g4) * QLDW + kt * 8 + t4;
            #pragma unroll
            for (int nt = 0; nt < 8; nt++) {
                uint32_t b0 = bp[nt * 8 * QLDW];
                uint32_t b1 = bp[nt * 8 * QLDW + 4];
                #pragma unroll
                for (int mt = 0; mt < 4; mt++)
                    mma16(acc[mt][nt], af[mt], b0, b1);
            }
        }
        __syncthreads();
    }

    // ---- epilogue: stage in smem, coalesced uint4 stores ----
    uint16_t* ep = (uint16_t*)sw;
    const bool is_v = (m0 == 512);
    const float sc = (m0 == 0) ? QSCALE : 1.0f;

    #pragma unroll
    for (int mt = 0; mt < 4; mt++) {
        const int r = wm * 64 + mt * 16 + g4;
        const float bv0 = bias[m0 + r], bv1 = bias[m0 + r + 8];
        #pragma unroll
        for (int nt = 0; nt < 8; nt++) {
            const int tl = wn * 64 + nt * 8 + 2 * t4;
            __half h0 = __float2half_rn((acc[mt][nt][0] + bv0) * sc);
            __half h1 = __float2half_rn((acc[mt][nt][1] + bv0) * sc);
            __half h2 = __float2half_rn((acc[mt][nt][2] + bv1) * sc);
            __half h3 = __float2half_rn((acc[mt][nt][3] + bv1) * sc);
            if (is_v) {
                // stage [row 0..255][tok pad 136]
                __half2 p01; p01.x = h0; p01.y = h1;
                __half2 p23; p23.x = h2; p23.y = h3;
                *(__half2*)&ep[(r)     * 136 + tl] = p01;
                *(__half2*)&ep[(r + 8) * 136 + tl] = p23;
            } else {
                // stage [tok 0..127][row pad 264]
                ep[(tl)     * 264 + r]     = __half_as_ushort(h0);
                ep[(tl + 1) * 264 + r]     = __half_as_ushort(h1);
                ep[(tl)     * 264 + r + 8] = __half_as_ushort(h2);
                ep[(tl + 1) * 264 + r + 8] = __half_as_ushort(h3);
            }
        }
    }
    __syncthreads();

    if (is_v) {
        #pragma unroll
        for (int e = tid; e < 4096; e += 256) {
            const int ch = e >> 4, c8 = e & 15;
            uint4 val = *(uint4*)&ep[ch * 136 + c8 * 8];
            __half* gv = g_vh + ((size_t)(bb * 4 + (ch >> 6)) * 64 + (ch & 63)) * HWSZ
                       + n0 + c8 * 8;
            *(uint4*)gv = val;
        }
    } else {
        __half* base = (m0 == 0) ? g_qh : g_kh;
        #pragma unroll
        for (int e = tid; e < 4096; e += 256) {
            const int a = e >> 5, c8 = e & 31;     // a = tok, c8 = row chunk
            uint4 val = *(uint4*)&ep[a * 264 + c8 * 8];
            const int rm = c8 * 8;                 // 0..255, head = rm>>6
            const int tok = n0 + a;
            __half* gp = base + ((size_t)(bb * 4 + (rm >> 6)) * HWSZ + tok) * 64 + (rm & 63);
            *(uint4*)gp = val;
        }
    }
}

// ============================================================
// proj GEMM (128x128, unchanged proven config)
// ============================================================
#define LDWH 20
#define TILEW (128 * LDWH)
#define GEMM_SMEM_BYTES (4 * TILEW * 4)

__global__ void __launch_bounds__(256, 2) gemm_proj_kernel(
        const __half* __restrict__ A,
        const __half* __restrict__ Bt,
        const float* __restrict__ bias,
        const float* __restrict__ resid,
        float* __restrict__ out) {
    extern __shared__ uint32_t sw[];
    uint32_t* a_s = sw;
    uint32_t* b_s = sw + 2 * TILEW;
    const uint32_t a_u = smem_u32(a_s);
    const uint32_t b_u = smem_u32(b_s);

    const int tid = threadIdx.x, lane = tid & 31, wid = tid >> 5;
    const int g4 = lane >> 2, t4 = lane & 3;
    const int wm = wid >> 1, wn = wid & 1;
    const int bb = blockIdx.z;
    const int m0 = blockIdx.y * 128;
    const int n0 = blockIdx.x * 128;
    const __half* Bp = Bt + (size_t)bb * HWSZ * 256 + (size_t)n0 * 256;

    float acc[2][8][4];
    #pragma unroll
    for (int mt = 0; mt < 2; mt++)
        #pragma unroll
        for (int nt = 0; nt < 8; nt++)
            #pragma unroll
            for (int i = 0; i < 4; i++) acc[mt][nt][i] = 0.f;

    #pragma unroll 2
    for (int e = tid; e < 512; e += 256) {
        int r = e >> 2, c8 = e & 3;
        cp16(a_u + (r * LDWH + c8 * 4) * 4, A + (size_t)(m0 + r) * 256 + c8 * 8);
    }
    #pragma unroll 2
    for (int e = tid; e < 512; e += 256) {
        int r = e >> 2, c8 = e & 3;
        cp16(b_u + (r * LDWH + c8 * 4) * 4, Bp + (size_t)r * 256 + c8 * 8);
    }
    CP_COMMIT();

    for (int j = 0; j < 8; j++) {
        const int buf = j & 1;
        const uint32_t* at = a_s + buf * TILEW;
        const uint32_t* bt = b_s + buf * TILEW;

        CP_WAIT0();
        __syncthreads();

        if (j < 7) {
            const uint32_t ad = a_u + ((buf ^ 1) * TILEW) * 4;
            const uint32_t bd = b_u + ((buf ^ 1) * TILEW) * 4;
            const int k0 = (j + 1) * 32;
            #pragma unroll 2
            for (int e = tid; e < 512; e += 256) {
                int r = e >> 2, c8 = e & 3;
                cp16(ad + (r * LDWH + c8 * 4) * 4, A + (size_t)(m0 + r) * 256 + k0 + c8 * 8);
            }
            #pragma unroll 2
            for (int e = tid; e < 512; e += 256) {
                int r = e >> 2, c8 = e & 3;
                cp16(bd + (r * LDWH + c8 * 4) * 4, Bp + (size_t)r * 256 + k0 + c8 * 8);
            }
            CP_COMMIT();
        }

        #pragma unroll
        for (int kt = 0; kt < 2; kt++) {
            uint32_t af[2][4];
            #pragma unroll
            for (int mt = 0; mt < 2; mt++) {
                const uint32_t* ap = at + (wm * 32 + mt * 16 + g4) * LDWH + kt * 8 + t4;
                af[mt][0] = ap[0];
                af[mt][1] = ap[8 * LDWH];
                af[mt][2] = ap[4];
                af[mt][3] = ap[8 * LDWH + 4];
            }
            const uint32_t* bp = bt + (wn * 64 + g4) * LDWH + kt * 8 + t4;
            #pragma unroll
            for (int nt = 0; nt < 8; nt++) {
                uint32_t b0 = bp[nt * 8 * LDWH];
                uint32_t b1 = bp[nt * 8 * LDWH + 4];
                mma16(acc[0][nt], af[0], b0, b1);
                mma16(acc[1][nt], af[1], b0, b1);
            }
        }
        __syncthreads();
    }

    #pragma unroll
    for (int mt = 0; mt < 2; mt++) {
        const int r0 = m0 + wm * 32 + mt * 16 + g4;
        const float bv0 = bias[r0], bv1 = bias[r0 + 8];
        #pragma unroll
        for (int nt = 0; nt < 8; nt++) {
            const int tok = n0 + wn * 64 + nt * 8 + 2 * t4;
            float v0 = acc[mt][nt][0] + bv0;
            float v1 = acc[mt][nt][1] + bv0;
            float v2 = acc[mt][nt][2] + bv1;
            float v3 = acc[mt][nt][3] + bv1;
            const float* rp = resid + ((size_t)bb * 256 + r0) * HWSZ + tok;
            float* op = out + ((size_t)bb * 256 + r0) * HWSZ + tok;
            float2 ra = *(const float2*)rp;
            float2 rb = *(const float2*)(rp + 8 * HWSZ);
            *(float2*)op              = make_float2(v0 + ra.x, v1 + ra.y);
            *(float2*)(op + 8 * HWSZ) = make_float2(v2 + rb.x, v3 + rb.y);
        }
    }
}

// ============================================================
// fp16 flash attention: BM=256 (unchanged from R12 best).
// ============================================================
#define LDW 36
#define KVW (64 * LDW)
#define ATTN_SMEM_BYTES (4 * KVW * 4)
#define ONE2 0x3C003C00u

__global__ void __launch_bounds__(256) attn_mma_kernel() {
    extern __shared__ uint32_t smw[];
    uint32_t* ks_base = smw;
    uint32_t* vs_base = smw + 2 * KVW;

    const int tid = threadIdx.x, lane = tid & 31, wid = tid >> 5;
    const int g4 = lane >> 2, t4 = lane & 3;
    const int bh = blockIdx.y;
    const int bb = bh >> 2, hh = bh & 3;
    const int i0 = blockIdx.x * 256;
    const int wrow = wid * 32;

    const __half* qg = g_qh + (size_t)bh * HWSZ * 64;
    const __half* kg = g_kh + (size_t)bh * HWSZ * 64;
    const __half* vg = g_vh + (size_t)bh * 64 * HWSZ;

    const uint32_t ks_u = smem_u32(ks_base);
    const uint32_t vs_u = smem_u32(vs_base);

    const int lm_m = lane >> 3;
    const uint32_t lm_row = (uint32_t)(((lm_m >> 1) * 8) + (lane & 7));
    const uint32_t lm_kb  = (uint32_t)((lm_m & 1) * 16);

    uint32_t qf[2][4][4];
    #pragma unroll
    for (int mt = 0; mt < 2; mt++) {
        const __half* qr0 = qg + (size_t)(i0 + wrow + mt * 16 + g4) * 64;
        const __half* qr1 = qr0 + 8 * 64;
        #pragma unroll
        for (int kt = 0; kt < 4; kt++) {
            qf[mt][kt][0] = *(const uint32_t*)(qr0 + kt * 16 + 2 * t4);
            qf[mt][kt][1] = *(const uint32_t*)(qr1 + kt * 16 + 2 * t4);
            qf[mt][kt][2] = *(const uint32_t*)(qr0 + kt * 16 + 2 * t4 + 8);
            qf[mt][kt][3] = *(const uint32_t*)(qr1 + kt * 16 + 2 * t4 + 8);
        }
    }

    float of[2][9][4];
    #pragma unroll
    for (int mt = 0; mt < 2; mt++)
        #pragma unroll
        for (int nt = 0; nt < 9; nt++)
            #pragma unroll
            for (int i = 0; i < 4; i++) of[mt][nt][i] = 0.f;

    #pragma unroll 2
    for (int e = tid; e < 512; e += 256) {
        int r = e >> 3, c = e & 7;
        cp16(ks_u + (r * LDW) * 4 + c * 16, kg + (size_t)r * 64 + c * 8);
    }
    #pragma unroll 2
    for (int e = tid; e < 512; e += 256) {
        int r = e >> 3, c = e & 7;
        cp16(vs_u + (r * LDW) * 4 + c * 16, vg + (size_t)r * HWSZ + c * 8);
    }
    CP_COMMIT();

    for (int j = 0; j < 64; j++) {
        const int buf = j & 1;
        const uint32_t klm = ks_u + (buf * KVW + lm_row * LDW) * 4 + lm_kb;
        const uint32_t vlm = vs_u + (buf * KVW + lm_row * LDW) * 4 + lm_kb;

        CP_WAIT0();
        __syncthreads();

        if (j < 63) {
            const uint32_t kd = ks_u + ((buf ^ 1) * KVW) * 4;
            const uint32_t vd = vs_u + ((buf ^ 1) * KVW) * 4;
            const __half* kn = kg + (size_t)(j + 1) * 64 * 64;
            const __half* vn = vg + (j + 1) * 64;
            #pragma unroll 2
            for (int e = tid; e < 512; e += 256) {
                int r = e >> 3, c = e & 7;
                cp16(kd + (r * LDW) * 4 + c * 16, kn + (size_t)r * 64 + c * 8);
            }
            #pragma unroll 2
            for (int e = tid; e < 512; e += 256) {
                int r = e >> 3, c = e & 7;
                cp16(vd + (r * LDW) * 4 + c * 16, vn + (size_t)r * HWSZ + c * 8);
            }
            CP_COMMIT();
        }

        float sf[2][8][4];
        #pragma unroll
        for (int mt = 0; mt < 2; mt++)
            #pragma unroll
            for (int nt = 0; nt < 8; nt++)
                #pragma unroll
                for (int i = 0; i < 4; i++) sf[mt][nt][i] = 0.f;

        #pragma unroll
        for (int kt = 0; kt < 4; kt++) {
            #pragma unroll
            for (int ntp = 0; ntp < 2; ntp++) {
                uint32_t br[4];
                ldsm4(br, klm + (ntp * 16 * LDW) * 4 + kt * 32);
                mma16(sf[0][2 * ntp],     qf[0][kt], br[0], br[1]);
                mma16(sf[1][2 * ntp],     qf[1][kt], br[0], br[1]);
                mma16(sf[0][2 * ntp + 1], qf[0][kt], br[2], br[3]);
                mma16(sf[1][2 * ntp + 1], qf[1][kt], br[2], br[3]);
            }
        }

        uint32_t pa[2][4][4];

        #pragma unroll
        for (int kt = 0; kt < 4; kt++) {
            #pragma unroll
            for (int ntp = 2; ntp < 4; ntp++) {
                uint32_t br[4];
                ldsm4(br, klm + (ntp * 16 * LDW) * 4 + kt * 32);
                mma16(sf[0][2 * ntp],     qf[0][kt], br[0], br[1]);
                mma16(sf[1][2 * ntp],     qf[1][kt], br[0], br[1]);
                mma16(sf[0][2 * ntp + 1], qf[0][kt], br[2], br[3]);
                mma16(sf[1][2 * ntp + 1], qf[1][kt], br[2], br[3]);
            }
        }
        #pragma unroll
        for (int mt = 0; mt < 2; mt++)
            #pragma unroll
            for (int nt = 0; nt < 4; nt++) {
                float p0 = ex2f(sf[mt][nt][0]);
                float p1 = ex2f(sf[mt][nt][1]);
                float p2 = ex2f(sf[mt][nt][2]);
                float p3 = ex2f(sf[mt][nt][3]);
                pa[mt][nt >> 1][(nt & 1) * 2]     = pack_h2(p0, p1);
                pa[mt][nt >> 1][(nt & 1) * 2 + 1] = pack_h2(p2, p3);
            }

        #pragma unroll
        for (int kt = 0; kt < 2; kt++) {
            #pragma unroll
            for (int ntp = 0; ntp < 4; ntp++) {
                uint32_t br[4];
                ldsm4(br, vlm + (ntp * 16 * LDW) * 4 + kt * 32);
                mma16(of[0][2 * ntp],     pa[0][kt], br[0], br[1]);
                mma16(of[1][2 * ntp],     pa[1][kt], br[0], br[1]);
                mma16(of[0][2 * ntp + 1], pa[0][kt], br[2], br[3]);
                mma16(of[1][2 * ntp + 1], pa[1][kt], br[2], br[3]);
            }
            mma16(of[0][8], pa[0][kt], ONE2, ONE2);
            mma16(of[1][8], pa[1][kt], ONE2, ONE2);
        }
        #pragma unroll
        for (int mt = 0; mt < 2; mt++)
            #pragma unroll
            for (int nt = 4; nt < 8; nt++) {
                float p0 = ex2f(sf[mt][nt][0]);
                float p1 = ex2f(sf[mt][nt][1]);
                float p2 = ex2f(sf[mt][nt][2]);
                float p3 = ex2f(sf[mt][nt][3]);
                pa[mt][nt >> 1][(nt & 1) * 2]     = pack_h2(p0, p1);
                pa[mt][nt >> 1][(nt & 1) * 2 + 1] = pack_h2(p2, p3);
            }

        #pragma unroll
        for (int kt = 2; kt < 4; kt++) {
            #pragma unroll
            for (int ntp = 0; ntp < 4; ntp++) {
                uint32_t br[4];
                ldsm4(br, vlm + (ntp * 16 * LDW) * 4 + kt * 32);
                mma16(of[0][2 * ntp],     pa[0][kt], br[0], br[1]);
                mma16(of[1][2 * ntp],     pa[1][kt], br[0], br[1]);
                mma16(of[0][2 * ntp + 1], pa[0][kt], br[2], br[3]);
                mma16(of[1][2 * ntp + 1], pa[1][kt], br[2], br[3]);
            }
            mma16(of[0][8], pa[0][kt], ONE2, ONE2);
            mma16(of[1][8], pa[1][kt], ONE2, ONE2);
        }
    }

    #pragma unroll
    for (int mt = 0; mt < 2; mt++) {
        float inv0 = 1.f / of[mt][8][0];
        float inv1 = 1.f / of[mt][8][2];
        int tok = i0 + wrow + mt * 16 + g4;
        __half* d0 = g_oh + ((size_t)bb * HWSZ + tok) * 256 + hh * 64;
        __half* d1 = d0 + 8 * 256;
        #pragma unroll
        for (int nt = 0; nt < 8; nt++) {
            int ch = nt * 8 + 2 * t4;
            *(__half2*)(d0 + ch) = __floats2half2_rn(of[mt][nt][0] * inv0,
                                                     of[mt][nt][1] * inv0);
            *(__half2*)(d1 + ch) = __floats2half2_rn(of[mt][nt][2] * inv1,
                                                     of[mt][nt][3] * inv1);
        }
    }
}

// ============================================================
extern "C" void kernel_launch(void* const* d_in, const int* in_sizes, int n_in,
                              void* d_out, int out_size) {
    const float* x      = (const float*)d_in[0];
    const float* norm_w = (const float*)d_in[1];
    const float* norm_b = (const float*)d_in[2];
    const float* qkv_w  = (const float*)d_in[3];
    const float* qkv_b  = (const float*)d_in[4];
    const float* proj_w = (const float*)d_in[5];
    const float* proj_b = (const float*)d_in[6];
    float* out = (float*)d_out;

    void *pht, *poh, *pwq, *pwp;
    cudaGetSymbolAddress(&pht, g_ht);
    cudaGetSymbolAddress(&poh, g_oh);
    cudaGetSymbolAddress(&pwq, g_wqkv);
    cudaGetSymbolAddress(&pwp, g_wproj);

    cudaFuncSetAttribute(gemm_qkv256_kernel,
                         cudaFuncAttributeMaxDynamicSharedMemorySize, QKV_SMEM_BYTES);
    cudaFuncSetAttribute(gemm_proj_kernel,
                         cudaFuncAttributeMaxDynamicSharedMemorySize, GEMM_SMEM_BYTES);
    cudaFuncSetAttribute(attn_mma_kernel,
                         cudaFuncAttributeMaxDynamicSharedMemorySize, ATTN_SMEM_BYTES);

    convert_w_kernel<<<320, 256>>>(qkv_w, proj_w);
    gn_partial_kernel<<<1024, 128>>>(x);
    gn_final_kernel<<<1, 32>>>();
    gn_norm_kernel<<<dim3(HWSZ / 128, 32), 256>>>(x, norm_w, norm_b);

    gemm_qkv256_kernel<<<dim3(HWSZ / 128, 3, BATCH), 256, QKV_SMEM_BYTES>>>(
        (const __half*)pwq, (const __half*)pht, qkv_b);

    attn_mma_kernel<<<dim3(HWSZ / 256, NBH), 256, ATTN_SMEM_BYTES>>>();

    gemm_proj_kernel<<<dim3(HWSZ / 128, 256 / 128, BATCH), 256, GEMM_SMEM_BYTES>>>(
        (const __half*)pwp, (const __half*)poh, proj_b, x, out);
}